// round 16
// baseline (speedup 1.0000x reference)
#include <cuda_runtime.h>
#include <cuda_bf16.h>
#include <cstdint>

#define H 128
#define MT 64
#define MAX_E 250000

#define SA128 136
#define SA48  56
#define SD    132

#define OFF_AH 0u
#define OFF_AL 17408u
#define OFF_BH 34816u
#define OFF_BL 69632u
#define OFF_D  0u
#define OFF_KJ 104448u
#define OFF_JI 104704u
#define SMEM_BYTES 105472

// ---------------- scratch ---------------------------------------------------
__device__ __align__(16) __nv_bfloat16 g_WH[7 * 16384];
__device__ __align__(16) __nv_bfloat16 g_WL[7 * 16384];
__device__ __align__(16) __nv_bfloat16 g_W1H[128 * 48];
__device__ __align__(16) __nv_bfloat16 g_W1L[128 * 48];
__device__ __align__(16) uint32_t      g_edge_p[(size_t)MAX_E * H];  // (hi,lo) packed
__device__ __align__(16) float         g_m[(size_t)MAX_E * H];

// ---------------- helpers ---------------------------------------------------
__device__ __forceinline__ uint32_t smem_u32(const void* p) {
    uint32_t a;
    asm("{ .reg .u64 t; cvta.to.shared.u64 t, %1; cvt.u32.u64 %0, t; }"
        : "=r"(a) : "l"(p));
    return a;
}
__device__ __forceinline__ void sp(float v, float& h, float& l) {
    h = __bfloat162float(__float2bfloat16(v));
    l = v - h;
}
__device__ __forceinline__ uint32_t pk2(float a, float b) {
    __nv_bfloat162 t = __floats2bfloat162_rn(a, b);
    return *(uint32_t*)&t;
}
__device__ __forceinline__ void prefetchL2(const void* p) {
    asm volatile("prefetch.global.L2 [%0];" :: "l"(p));
}
// Unpack (hi,lo) word -> fp32 value hi+lo.
__device__ __forceinline__ float unpk(uint32_t w) {
    __nv_bfloat162 t = *(__nv_bfloat162*)&w;
    return __bfloat162float(t.x) + __bfloat162float(t.y);
}

// 5-instruction silu: x * rcp(1 + ex2(-x*log2e)). Saturation limits are exact.
__device__ __forceinline__ float fast_silu(float x) {
    float e, r;
    asm("ex2.approx.f32 %0, %1;" : "=f"(e) : "f"(x * -1.4426950408889634f));
    asm("rcp.approx.f32 %0, %1;" : "=f"(r) : "f"(1.0f + e));
    return x * r;
}

// ---------------- cp.async ---------------------------------------------------
__device__ __forceinline__ void cpa16(uint32_t dst, const void* src) {
    asm volatile("cp.async.cg.shared.global [%0], [%1], 16;" :: "r"(dst), "l"(src));
}
#define CP_COMMIT() asm volatile("cp.async.commit_group;" ::: "memory")
#define CP_WAIT0()  asm volatile("cp.async.wait_group 0;" ::: "memory")

template <int KB, int NT>
__device__ __forceinline__ void copyB_async(uint32_t Bh, uint32_t Bl,
                                            const __nv_bfloat16* __restrict__ sH,
                                            const __nv_bfloat16* __restrict__ sL) {
    const int SEG = KB / 8;
    for (int i = threadIdx.x; i < 128 * SEG; i += NT) {
        int r = i / SEG, s = i - r * SEG;
        uint32_t off = (uint32_t)((r * (KB + 8) + s * 8) * 2);
        cpa16(Bh + off, sH + i * 8);
        cpa16(Bl + off, sL + i * 8);
    }
    CP_COMMIT();
}

// ---------------- mma + ldmatrix --------------------------------------------
__device__ __forceinline__ void mma_bf16(float* d, const uint32_t* a, const uint32_t* b) {
    asm volatile(
        "mma.sync.aligned.m16n8k16.row.col.f32.bf16.bf16.f32 "
        "{%0,%1,%2,%3}, {%4,%5,%6,%7}, {%8,%9}, {%0,%1,%2,%3};"
        : "+f"(d[0]), "+f"(d[1]), "+f"(d[2]), "+f"(d[3])
        : "r"(a[0]), "r"(a[1]), "r"(a[2]), "r"(a[3]), "r"(b[0]), "r"(b[1]));
}
__device__ __forceinline__ void ldsm4(uint32_t* r, uint32_t addr) {
    asm volatile("ldmatrix.sync.aligned.m8n8.x4.shared.b16 {%0,%1,%2,%3}, [%4];"
                 : "=r"(r[0]), "=r"(r[1]), "=r"(r[2]), "=r"(r[3]) : "r"(addr));
}

// Warp tile: 32 x (NI*8). NI=4 -> 8 warps (2x4); NI=8 -> 4 warps (2x2).
// 3-pass split: AhBh + AlBh + AhBl. Single-buffered (ptxas pipelines it).
template <int KB, int SA, int NI>
__device__ __forceinline__ void warp_gemm(uint32_t sb, float (&acc)[2][NI][4]) {
    constexpr int NCW = 128 / (8 * NI);
    const int lane = threadIdx.x & 31, w = threadIdx.x >> 5;
    const int wr = w / NCW, wc = w % NCW;
    const int mrow = lane & 7, msel = lane >> 3;
    const uint32_t aoff0 = 2u * ((wr * 32 + (msel & 1) * 8 + mrow) * SA + (msel >> 1) * 8);
    const uint32_t aoff1 = aoff0 + 2u * 16 * SA;
    uint32_t boff[NI / 2];
#pragma unroll
    for (int p = 0; p < NI / 2; ++p)
        boff[p] = 2u * ((wc * (NI * 8) + p * 16 + (msel >> 1) * 8 + mrow) * SA + (msel & 1) * 8);

#pragma unroll
    for (int mi = 0; mi < 2; ++mi)
#pragma unroll
        for (int ni = 0; ni < NI; ++ni)
#pragma unroll
            for (int q = 0; q < 4; ++q) acc[mi][ni][q] = 0.f;

#pragma unroll
    for (int k0 = 0; k0 < KB; k0 += 16) {
        const uint32_t kb = 2u * k0;
        uint32_t ah[2][4], al[2][4], bh[NI / 2][4], bl[NI / 2][4];
        ldsm4(ah[0], sb + OFF_AH + aoff0 + kb);
        ldsm4(ah[1], sb + OFF_AH + aoff1 + kb);
#pragma unroll
        for (int p = 0; p < NI / 2; ++p)
            ldsm4(bh[p], sb + OFF_BH + boff[p] + kb);
        ldsm4(al[0], sb + OFF_AL + aoff0 + kb);
        ldsm4(al[1], sb + OFF_AL + aoff1 + kb);
#pragma unroll
        for (int p = 0; p < NI / 2; ++p)
            ldsm4(bl[p], sb + OFF_BL + boff[p] + kb);
#pragma unroll
        for (int mi = 0; mi < 2; ++mi)
#pragma unroll
            for (int p = 0; p < NI / 2; ++p) {
                mma_bf16(acc[mi][2 * p + 0], ah[mi], &bh[p][0]);
                mma_bf16(acc[mi][2 * p + 1], ah[mi], &bh[p][2]);
            }
#pragma unroll
        for (int mi = 0; mi < 2; ++mi)
#pragma unroll
            for (int p = 0; p < NI / 2; ++p) {
                mma_bf16(acc[mi][2 * p + 0], al[mi], &bh[p][0]);
                mma_bf16(acc[mi][2 * p + 1], al[mi], &bh[p][2]);
            }
#pragma unroll
        for (int mi = 0; mi < 2; ++mi)
#pragma unroll
            for (int p = 0; p < NI / 2; ++p) {
                mma_bf16(acc[mi][2 * p + 0], ah[mi], &bl[p][0]);
                mma_bf16(acc[mi][2 * p + 1], ah[mi], &bl[p][2]);
            }
    }
}

template <int NI>
__device__ __forceinline__ void acc_to_D(float* D, float (&acc)[2][NI][4]) {
    constexpr int NCW = 128 / (8 * NI);
    const int lane = threadIdx.x & 31, w = threadIdx.x >> 5;
    const int wr = w / NCW, wc = w % NCW;
    const int r4 = lane >> 2, kq = lane & 3;
#pragma unroll
    for (int mi = 0; mi < 2; ++mi) {
        int row = wr * 32 + mi * 16 + r4;
#pragma unroll
        for (int ni = 0; ni < NI; ++ni) {
            int col = wc * (NI * 8) + ni * 8 + kq * 2;
            *(float2*)&D[row * SD + col] = make_float2(acc[mi][ni][0], acc[mi][ni][1]);
            *(float2*)&D[(row + 8) * SD + col] = make_float2(acc[mi][ni][2], acc[mi][ni][3]);
        }
    }
}

template <int NI>
__device__ __forceinline__ void frag_store_split(char* Ah, char* Al,
                                                 const float (&a)[2][NI][4],
                                                 int wr, int wc, int qr, int kq) {
#pragma unroll
    for (int mi = 0; mi < 2; ++mi)
#pragma unroll
        for (int h2 = 0; h2 < 2; ++h2) {
            int row = wr * 32 + mi * 16 + h2 * 8 + qr;
#pragma unroll
            for (int ni = 0; ni < NI; ++ni) {
                int col = wc * (NI * 8) + ni * 8 + kq * 2;
                float v0 = a[mi][ni][h2 * 2 + 0], v1 = a[mi][ni][h2 * 2 + 1];
                float h0, l0, h1, l1;
                sp(v0, h0, l0); sp(v1, h1, l1);
                uint32_t off = 2u * (row * SA128 + col);
                *(uint32_t*)(Ah + off) = pk2(h0, h1);
                *(uint32_t*)(Al + off) = pk2(l0, l1);
            }
        }
}

template <int NI>
__device__ __forceinline__ void bias_frag(const float* __restrict__ b,
                                          int wc, int kq, float2 (&o)[NI]) {
#pragma unroll
    for (int ni = 0; ni < NI; ++ni)
        o[ni] = *(const float2*)&b[wc * (NI * 8) + ni * 8 + kq * 2];
}

// ---------------- fills ------------------------------------------------------
__device__ __forceinline__ void split_store4(char* Ah, char* Al, int eoff, float4 v) {
    float h0, l0, h1, l1, h2, l2, h3, l3;
    sp(v.x, h0, l0); sp(v.y, h1, l1); sp(v.z, h2, l2); sp(v.w, h3, l3);
    *(uint2*)(Ah + 2 * eoff) = make_uint2(pk2(h0, h1), pk2(h2, h3));
    *(uint2*)(Al + 2 * eoff) = make_uint2(pk2(l0, l1), pk2(l2, l3));
}

template <int NT>
__device__ __forceinline__ void fill_A128(char* Ah, char* Al,
                                          const float* __restrict__ src,
                                          long r0, int nrows) {
    for (int i = threadIdx.x; i < MT * 32; i += NT) {
        int r = i >> 5, c = (i & 31) * 4;
        float4 v = (r < nrows) ? *(const float4*)&src[(r0 + r) * H + c]
                               : make_float4(0.f, 0.f, 0.f, 0.f);
        split_store4(Ah, Al, r * SA128 + c, v);
    }
}

// ---------------- small kernels ---------------------------------------------
__global__ void zero_m_kernel(size_t n4) {
    float4 z = make_float4(0.f, 0.f, 0.f, 0.f);
    for (size_t i = (size_t)blockIdx.x * blockDim.x + threadIdx.x; i < n4;
         i += (size_t)gridDim.x * blockDim.x)
        ((float4*)g_m)[i] = z;
}

__global__ void prep_kernel(const float* __restrict__ Wkj, const float* __restrict__ Wrbf2,
                            const float* __restrict__ Wdown, const float* __restrict__ Wsbf2,
                            const float* __restrict__ Wup, const float* __restrict__ Wr1a,
                            const float* __restrict__ Wr1b, const float* __restrict__ Wsbf1) {
    int idx = blockIdx.x * 256 + threadIdx.x;
    if (idx < 7 * 16384) {
        int mat = idx >> 14, rem = idx & 16383;
        int n = rem >> 7, k = rem & 127;
        const float* Ws[7] = {Wkj, Wrbf2, Wdown, Wsbf2, Wup, Wr1a, Wr1b};
        float v = Ws[mat][k * H + n];
        float h, l; sp(v, h, l);
        g_WH[idx] = __float2bfloat16(h);
        g_WL[idx] = __float2bfloat16(l);
    } else {
        int rem = idx - 7 * 16384;
        if (rem < 128 * 48) {
            int n = rem / 48, k = rem - n * 48;
            float v = (k < 42) ? Wsbf1[k * H + n] : 0.f;
            float h, l; sp(v, h, l);
            g_W1H[rem] = __float2bfloat16(h);
            g_W1L[rem] = __float2bfloat16(l);
        }
    }
}

// ---------------- main kernels ----------------------------------------------
// K1 (256 threads, NI=4): edge_down = silu((silu(x@Wkj+b)*silu(rbf@Wr2+b))@Wdown+b)
__global__ __launch_bounds__(256, 2)
void edge_kernel(const float* __restrict__ x, const float* __restrict__ rbf,
                 const float* __restrict__ b_kj, const float* __restrict__ b_rbf2,
                 const float* __restrict__ b_down, int E) {
    extern __shared__ __align__(16) char sm[];
    uint32_t sb = smem_u32(sm);
    char* Ah = sm + OFF_AH; char* Al = sm + OFF_AL;
    float* D = (float*)(sm + OFF_D);
    const int tid = threadIdx.x, lane = tid & 31, w = tid >> 5;
    const int wr = w >> 2, wc = w & 3, qr = lane >> 2, kq = lane & 3;
    const long e0 = (long)blockIdx.x * MT;
    const int rows = (int)min((long)MT, (long)E - e0);
    float acc[2][4][4], t1[2][4][4];

    copyB_async<128, 256>(sb + OFF_BH, sb + OFF_BL, g_WH + 0 * 16384, g_WL + 0 * 16384);
    fill_A128<256>(Ah, Al, x, e0, rows);
    CP_WAIT0(); __syncthreads();
    warp_gemm<128, SA128, 4>(sb, acc);
    __syncthreads();
    copyB_async<128, 256>(sb + OFF_BH, sb + OFF_BL, g_WH + 1 * 16384, g_WL + 1 * 16384);
    {
        float2 b2[4]; bias_frag<4>(b_kj, wc, kq, b2);
#pragma unroll
        for (int mi = 0; mi < 2; ++mi)
#pragma unroll
            for (int ni = 0; ni < 4; ++ni) {
                t1[mi][ni][0] = fast_silu(acc[mi][ni][0] + b2[ni].x);
                t1[mi][ni][1] = fast_silu(acc[mi][ni][1] + b2[ni].y);
                t1[mi][ni][2] = fast_silu(acc[mi][ni][2] + b2[ni].x);
                t1[mi][ni][3] = fast_silu(acc[mi][ni][3] + b2[ni].y);
            }
    }
    fill_A128<256>(Ah, Al, rbf, e0, rows);
    CP_WAIT0(); __syncthreads();

    warp_gemm<128, SA128, 4>(sb, acc);
    __syncthreads();
    copyB_async<128, 256>(sb + OFF_BH, sb + OFF_BL, g_WH + 2 * 16384, g_WL + 2 * 16384);
    {
        float2 b2[4]; bias_frag<4>(b_rbf2, wc, kq, b2);
#pragma unroll
        for (int mi = 0; mi < 2; ++mi)
#pragma unroll
            for (int ni = 0; ni < 4; ++ni) {
                acc[mi][ni][0] = t1[mi][ni][0] * fast_silu(acc[mi][ni][0] + b2[ni].x);
                acc[mi][ni][1] = t1[mi][ni][1] * fast_silu(acc[mi][ni][1] + b2[ni].y);
                acc[mi][ni][2] = t1[mi][ni][2] * fast_silu(acc[mi][ni][2] + b2[ni].x);
                acc[mi][ni][3] = t1[mi][ni][3] * fast_silu(acc[mi][ni][3] + b2[ni].y);
            }
    }
    frag_store_split<4>(Ah, Al, acc, wr, wc, qr, kq);
    CP_WAIT0(); __syncthreads();

    warp_gemm<128, SA128, 4>(sb, acc);
    __syncthreads();
    acc_to_D<4>(D, acc);
    __syncthreads();
    {
        const int row = tid >> 2, c0 = (tid & 3) * 32;
        if (row < rows) {
            uint32_t* op = g_edge_p + (size_t)(e0 + row) * H + c0;
#pragma unroll
            for (int g = 0; g < 8; ++g) {
                float4 d = *(const float4*)&D[row * SD + c0 + g * 4];
                float4 b = *(const float4*)&b_down[c0 + g * 4];
                float o0 = fast_silu(d.x + b.x), o1 = fast_silu(d.y + b.y);
                float o2 = fast_silu(d.z + b.z), o3 = fast_silu(d.w + b.w);
                float h0, l0, h1, l1, h2, l2, h3, l3;
                sp(o0, h0, l0); sp(o1, h1, l1); sp(o2, h2, l2); sp(o3, h3, l3);
                uint4 pw;
                pw.x = pk2(h0, l0); pw.y = pk2(h1, l1);
                pw.z = pk2(h2, l2); pw.w = pk2(h3, l3);
                *(uint4*)(op + g * 4) = pw;
            }
        }
    }
}

// K2 (128 threads, NI=8): s=silu(silu(sbf@W1)@W2); o=silu((edge[idx_kj]*s)@Wup+b)
// S2 scatters DIRECTLY from fragments via red.v2.
__global__ __launch_bounds__(128, 2)
void trip_kernel(const float* __restrict__ sbf, const int* __restrict__ idx_kj,
                 const int* __restrict__ idx_ji, const float* __restrict__ b_up, int T) {
    extern __shared__ __align__(16) char sm[];
    uint32_t sb = smem_u32(sm);
    char* Ah = sm + OFF_AH; char* Al = sm + OFF_AL;
    int* skj = (int*)(sm + OFF_KJ);
    int* sji = (int*)(sm + OFF_JI);
    const int tid = threadIdx.x, lane = tid & 31, w = tid >> 5;
    const int wr = w >> 1, wc = w & 1, qr = lane >> 2, kq = lane & 3;
    const long t0 = (long)blockIdx.x * MT;
    const int rows = (int)min((long)MT, (long)T - t0);
    float acc[2][8][4];

    if (tid < MT) {
        long t = t0 + tid;
        skj[tid] = (tid < rows) ? idx_kj[t] : 0;
        sji[tid] = (tid < rows) ? idx_ji[t] : 0;
    }

    // S0: sbf @ Wsbf1 at K=48 (cols 42..47 zero)
    copyB_async<48, 128>(sb + OFF_BH, sb + OFF_BL, g_W1H, g_W1L);
    for (int i = tid; i < MT * 48; i += 128) {
        int r = i / 48, c = i - r * 48;
        float val = (c < 42 && r < rows) ? sbf[(t0 + r) * 42 + c] : 0.f;
        float h, l; sp(val, h, l);
        *(__nv_bfloat16*)(Ah + (r * SA48 + c) * 2) = __float2bfloat16(h);
        *(__nv_bfloat16*)(Al + (r * SA48 + c) * 2) = __float2bfloat16(l);
    }
    CP_WAIT0(); __syncthreads();
    warp_gemm<48, SA48, 8>(sb, acc);
    __syncthreads();
    copyB_async<128, 128>(sb + OFF_BH, sb + OFF_BL, g_WH + 3 * 16384, g_WL + 3 * 16384);
#pragma unroll
    for (int mi = 0; mi < 2; ++mi)
#pragma unroll
        for (int ni = 0; ni < 8; ++ni)
#pragma unroll
            for (int q = 0; q < 4; ++q) acc[mi][ni][q] = fast_silu(acc[mi][ni][q]);
    frag_store_split<8>(Ah, Al, acc, wr, wc, qr, kq);
#pragma unroll
    for (int mi = 0; mi < 2; ++mi)
#pragma unroll
        for (int h2 = 0; h2 < 2; ++h2) {
            int row = wr * 32 + mi * 16 + h2 * 8 + qr;
            size_t e = (size_t)skj[row];
            prefetchL2(g_edge_p + e * H + wc * 64);
        }
    CP_WAIT0(); __syncthreads();

    // S1: @ Wsbf2 ; multiply gathered packed edge_down
    warp_gemm<128, SA128, 8>(sb, acc);
    __syncthreads();
    copyB_async<128, 128>(sb + OFF_BH, sb + OFF_BL, g_WH + 4 * 16384, g_WL + 4 * 16384);
#pragma unroll
    for (int mi = 0; mi < 2; ++mi)
#pragma unroll
        for (int h2 = 0; h2 < 2; ++h2) {
            int row = wr * 32 + mi * 16 + h2 * 8 + qr;
            size_t e = (size_t)skj[row];
            const uint32_t* pp = g_edge_p + e * H + wc * 64 + kq * 2;
#pragma unroll
            for (int ni = 0; ni < 8; ++ni) {
                uint2 pw = *(const uint2*)(pp + ni * 8);
                acc[mi][ni][h2 * 2 + 0] = fast_silu(acc[mi][ni][h2 * 2 + 0]) * unpk(pw.x);
                acc[mi][ni][h2 * 2 + 1] = fast_silu(acc[mi][ni][h2 * 2 + 1]) * unpk(pw.y);
            }
        }
    frag_store_split<8>(Ah, Al, acc, wr, wc, qr, kq);
    CP_WAIT0(); __syncthreads();

    // S2: @ Wup -> silu(.+b_up) -> fragment-direct scatter
    warp_gemm<128, SA128, 8>(sb, acc);
    {
        float2 b2[8]; bias_frag<8>(b_up, wc, kq, b2);
#pragma unroll
        for (int mi = 0; mi < 2; ++mi)
#pragma unroll
            for (int h2 = 0; h2 < 2; ++h2) {
                int row = wr * 32 + mi * 16 + h2 * 8 + qr;
                if (row < rows) {
                    float* mp = g_m + (size_t)sji[row] * H + wc * 64 + kq * 2;
#pragma unroll
                    for (int ni = 0; ni < 8; ++ni) {
                        float o0 = fast_silu(acc[mi][ni][h2 * 2 + 0] + b2[ni].x);
                        float o1 = fast_silu(acc[mi][ni][h2 * 2 + 1] + b2[ni].y);
                        asm volatile("red.global.add.v2.f32 [%0], {%1,%2};"
                                     :: "l"(mp + ni * 8), "f"(o0), "f"(o1)
                                     : "memory");
                    }
                }
            }
    }
}

// K3 (256 threads, NI=4): out = m + silu(silu(m@Wr1a+b)@Wr1b+b) + x
__global__ __launch_bounds__(256, 2)
void res_kernel(const float* __restrict__ x, const float* __restrict__ b_r1a,
                const float* __restrict__ b_r1b, float* __restrict__ out, int E) {
    extern __shared__ __align__(16) char sm[];
    uint32_t sb = smem_u32(sm);
    char* Ah = sm + OFF_AH; char* Al = sm + OFF_AL;
    float* D = (float*)(sm + OFF_D);
    const int tid = threadIdx.x, lane = tid & 31, w = tid >> 5;
    const int wr = w >> 2, wc = w & 3, qr = lane >> 2, kq = lane & 3;
    const long e0 = (long)blockIdx.x * MT;
    const int rows = (int)min((long)MT, (long)E - e0);
    float acc[2][4][4];

    copyB_async<128, 256>(sb + OFF_BH, sb + OFF_BL, g_WH + 5 * 16384, g_WL + 5 * 16384);
    fill_A128<256>(Ah, Al, g_m, e0, rows);
    CP_WAIT0(); __syncthreads();
    warp_gemm<128, SA128, 4>(sb, acc);
    __syncthreads();
    copyB_async<128, 256>(sb + OFF_BH, sb + OFF_BL, g_WH + 6 * 16384, g_WL + 6 * 16384);
    {
        float2 b2[4]; bias_frag<4>(b_r1a, wc, kq, b2);
#pragma unroll
        for (int mi = 0; mi < 2; ++mi)
#pragma unroll
            for (int ni = 0; ni < 4; ++ni) {
                acc[mi][ni][0] = fast_silu(acc[mi][ni][0] + b2[ni].x);
                acc[mi][ni][1] = fast_silu(acc[mi][ni][1] + b2[ni].y);
                acc[mi][ni][2] = fast_silu(acc[mi][ni][2] + b2[ni].x);
                acc[mi][ni][3] = fast_silu(acc[mi][ni][3] + b2[ni].y);
            }
    }
    frag_store_split<4>(Ah, Al, acc, wr, wc, qr, kq);
    CP_WAIT0(); __syncthreads();

    warp_gemm<128, SA128, 4>(sb, acc);
    __syncthreads();
    acc_to_D<4>(D, acc);
    __syncthreads();
    {
        const int row = tid >> 2, c0 = (tid & 3) * 32;
        if (row < rows) {
            const float4* mp = (const float4*)(g_m + (size_t)(e0 + row) * H + c0);
            const float4* xp = (const float4*)(x + (size_t)(e0 + row) * H + c0);
            float4* op = (float4*)(out + (size_t)(e0 + row) * H + c0);
#pragma unroll
            for (int g = 0; g < 8; ++g) {
                float4 d = *(const float4*)&D[row * SD + c0 + g * 4];
                float4 b = *(const float4*)&b_r1b[c0 + g * 4];
                float4 mv = mp[g], xv = xp[g], o;
                o.x = mv.x + fast_silu(d.x + b.x) + xv.x;
                o.y = mv.y + fast_silu(d.y + b.y) + xv.y;
                o.z = mv.z + fast_silu(d.z + b.z) + xv.z;
                o.w = mv.w + fast_silu(d.w + b.w) + xv.w;
                op[g] = o;
            }
        }
    }
}

// ---------------------------------------------------------------------------
extern "C" void kernel_launch(void* const* d_in, const int* in_sizes, int n_in,
                              void* d_out, int out_size) {
    const float* x      = (const float*)d_in[0];
    const float* rbf    = (const float*)d_in[1];
    const float* sbf    = (const float*)d_in[2];
    const int*   idx_kj = (const int*)d_in[3];
    const int*   idx_ji = (const int*)d_in[4];
    const float* W_rbf2 = (const float*)d_in[5];
    const float* b_rbf2 = (const float*)d_in[6];
    const float* W_sbf1 = (const float*)d_in[7];
    const float* W_sbf2 = (const float*)d_in[8];
    const float* W_kj   = (const float*)d_in[9];
    const float* b_kj   = (const float*)d_in[10];
    const float* W_down = (const float*)d_in[11];
    const float* b_down = (const float*)d_in[12];
    const float* W_up   = (const float*)d_in[13];
    const float* b_up   = (const float*)d_in[14];
    const float* W_r1a  = (const float*)d_in[15];
    const float* b_r1a  = (const float*)d_in[16];
    const float* W_r1b  = (const float*)d_in[17];
    const float* b_r1b  = (const float*)d_in[18];
    float* out = (float*)d_out;

    int E = in_sizes[0] / H;
    int T = in_sizes[3];

    cudaFuncSetAttribute(edge_kernel, cudaFuncAttributeMaxDynamicSharedMemorySize, SMEM_BYTES);
    cudaFuncSetAttribute(trip_kernel, cudaFuncAttributeMaxDynamicSharedMemorySize, SMEM_BYTES);
    cudaFuncSetAttribute(res_kernel, cudaFuncAttributeMaxDynamicSharedMemorySize, SMEM_BYTES);

    prep_kernel<<<480, 256>>>(W_kj, W_rbf2, W_down, W_sbf2, W_up, W_r1a, W_r1b, W_sbf1);
    zero_m_kernel<<<2048, 256>>>((size_t)E * H / 4);
    edge_kernel<<<(E + MT - 1) / MT, 256, SMEM_BYTES>>>(x, rbf, b_kj, b_rbf2, b_down, E);
    trip_kernel<<<(T + MT - 1) / MT, 128, SMEM_BYTES>>>(sbf, idx_kj, idx_ji, b_up, T);
    res_kernel<<<(E + MT - 1) / MT, 256, SMEM_BYTES>>>(x, b_r1a, b_r1b, out, E);
}

// round 17
// speedup vs baseline: 1.0294x; 1.0294x over previous
#include <cuda_runtime.h>
#include <cuda_bf16.h>
#include <cstdint>

#define H 128
#define MT 64
#define MAX_E 250000

#define SA128 136
#define SA64  72
#define SD    132

#define OFF_AH 0u
#define OFF_AL 17408u
#define OFF_BH 34816u
#define OFF_BL 69632u
#define OFF_D  0u
#define OFF_KJ 104448u
#define OFF_JI 104704u
#define SMEM_BYTES 105472

// ---------------- scratch ---------------------------------------------------
__device__ __align__(16) __nv_bfloat16 g_WH[7 * 16384];
__device__ __align__(16) __nv_bfloat16 g_WL[7 * 16384];
__device__ __align__(16) __nv_bfloat16 g_W1H[8192];
__device__ __align__(16) __nv_bfloat16 g_W1L[8192];
__device__ __align__(16) uint32_t      g_edge_p[(size_t)MAX_E * H];  // (hi,lo) packed
__device__ __align__(16) float         g_m[(size_t)MAX_E * H];

// ---------------- helpers ---------------------------------------------------
__device__ __forceinline__ uint32_t smem_u32(const void* p) {
    uint32_t a;
    asm("{ .reg .u64 t; cvta.to.shared.u64 t, %1; cvt.u32.u64 %0, t; }"
        : "=r"(a) : "l"(p));
    return a;
}
__device__ __forceinline__ void sp(float v, float& h, float& l) {
    h = __bfloat162float(__float2bfloat16(v));
    l = v - h;
}
__device__ __forceinline__ uint32_t pk2(float a, float b) {
    __nv_bfloat162 t = __floats2bfloat162_rn(a, b);
    return *(uint32_t*)&t;
}
__device__ __forceinline__ void prefetchL2(const void* p) {
    asm volatile("prefetch.global.L2 [%0];" :: "l"(p));
}
// Unpack (hi,lo) word -> fp32 value hi+lo.
__device__ __forceinline__ float unpk(uint32_t w) {
    __nv_bfloat162 t = *(__nv_bfloat162*)&w;
    return __bfloat162float(t.x) + __bfloat162float(t.y);
}

// 5-instruction silu: x * rcp(1 + ex2(-x*log2e)). Saturation limits are exact.
__device__ __forceinline__ float fast_silu(float x) {
    float e, r;
    asm("ex2.approx.f32 %0, %1;" : "=f"(e) : "f"(x * -1.4426950408889634f));
    asm("rcp.approx.f32 %0, %1;" : "=f"(r) : "f"(1.0f + e));
    return x * r;
}

// ---------------- cp.async ---------------------------------------------------
__device__ __forceinline__ void cpa16(uint32_t dst, const void* src) {
    asm volatile("cp.async.cg.shared.global [%0], [%1], 16;" :: "r"(dst), "l"(src));
}
#define CP_COMMIT() asm volatile("cp.async.commit_group;" ::: "memory")
#define CP_WAIT0()  asm volatile("cp.async.wait_group 0;" ::: "memory")

template <int KB, int NT>
__device__ __forceinline__ void copyB_async(uint32_t Bh, uint32_t Bl,
                                            const __nv_bfloat16* __restrict__ sH,
                                            const __nv_bfloat16* __restrict__ sL) {
    const int SEG = KB / 8;
    for (int i = threadIdx.x; i < 128 * SEG; i += NT) {
        int r = i / SEG, s = i - r * SEG;
        uint32_t off = (uint32_t)((r * (KB + 8) + s * 8) * 2);
        cpa16(Bh + off, sH + i * 8);
        cpa16(Bl + off, sL + i * 8);
    }
    CP_COMMIT();
}

// ---------------- mma + ldmatrix --------------------------------------------
__device__ __forceinline__ void mma_bf16(float* d, const uint32_t* a, const uint32_t* b) {
    asm volatile(
        "mma.sync.aligned.m16n8k16.row.col.f32.bf16.bf16.f32 "
        "{%0,%1,%2,%3}, {%4,%5,%6,%7}, {%8,%9}, {%0,%1,%2,%3};"
        : "+f"(d[0]), "+f"(d[1]), "+f"(d[2]), "+f"(d[3])
        : "r"(a[0]), "r"(a[1]), "r"(a[2]), "r"(a[3]), "r"(b[0]), "r"(b[1]));
}
__device__ __forceinline__ void ldsm4(uint32_t* r, uint32_t addr) {
    asm volatile("ldmatrix.sync.aligned.m8n8.x4.shared.b16 {%0,%1,%2,%3}, [%4];"
                 : "=r"(r[0]), "=r"(r[1]), "=r"(r[2]), "=r"(r[3]) : "r"(addr));
}

// Warp tile: 32 x (NI*8). NI=4 -> 8 warps (2x4); NI=8 -> 4 warps (2x2).
// 3-pass split: AhBh + AlBh + AhBl. Single-buffered (ptxas pipelines it).
template <int KB, int SA, int NI>
__device__ __forceinline__ void warp_gemm(uint32_t sb, float (&acc)[2][NI][4]) {
    constexpr int NCW = 128 / (8 * NI);
    const int lane = threadIdx.x & 31, w = threadIdx.x >> 5;
    const int wr = w / NCW, wc = w % NCW;
    const int mrow = lane & 7, msel = lane >> 3;
    const uint32_t aoff0 = 2u * ((wr * 32 + (msel & 1) * 8 + mrow) * SA + (msel >> 1) * 8);
    const uint32_t aoff1 = aoff0 + 2u * 16 * SA;
    uint32_t boff[NI / 2];
#pragma unroll
    for (int p = 0; p < NI / 2; ++p)
        boff[p] = 2u * ((wc * (NI * 8) + p * 16 + (msel >> 1) * 8 + mrow) * SA + (msel & 1) * 8);

#pragma unroll
    for (int mi = 0; mi < 2; ++mi)
#pragma unroll
        for (int ni = 0; ni < NI; ++ni)
#pragma unroll
            for (int q = 0; q < 4; ++q) acc[mi][ni][q] = 0.f;

#pragma unroll
    for (int k0 = 0; k0 < KB; k0 += 16) {
        const uint32_t kb = 2u * k0;
        uint32_t ah[2][4], al[2][4], bh[NI / 2][4], bl[NI / 2][4];
        ldsm4(ah[0], sb + OFF_AH + aoff0 + kb);
        ldsm4(ah[1], sb + OFF_AH + aoff1 + kb);
#pragma unroll
        for (int p = 0; p < NI / 2; ++p)
            ldsm4(bh[p], sb + OFF_BH + boff[p] + kb);
        ldsm4(al[0], sb + OFF_AL + aoff0 + kb);
        ldsm4(al[1], sb + OFF_AL + aoff1 + kb);
#pragma unroll
        for (int p = 0; p < NI / 2; ++p)
            ldsm4(bl[p], sb + OFF_BL + boff[p] + kb);
#pragma unroll
        for (int mi = 0; mi < 2; ++mi)
#pragma unroll
            for (int p = 0; p < NI / 2; ++p) {
                mma_bf16(acc[mi][2 * p + 0], ah[mi], &bh[p][0]);
                mma_bf16(acc[mi][2 * p + 1], ah[mi], &bh[p][2]);
            }
#pragma unroll
        for (int mi = 0; mi < 2; ++mi)
#pragma unroll
            for (int p = 0; p < NI / 2; ++p) {
                mma_bf16(acc[mi][2 * p + 0], al[mi], &bh[p][0]);
                mma_bf16(acc[mi][2 * p + 1], al[mi], &bh[p][2]);
            }
#pragma unroll
        for (int mi = 0; mi < 2; ++mi)
#pragma unroll
            for (int p = 0; p < NI / 2; ++p) {
                mma_bf16(acc[mi][2 * p + 0], ah[mi], &bl[p][0]);
                mma_bf16(acc[mi][2 * p + 1], ah[mi], &bl[p][2]);
            }
    }
}

template <int NI>
__device__ __forceinline__ void acc_to_D(float* D, float (&acc)[2][NI][4]) {
    constexpr int NCW = 128 / (8 * NI);
    const int lane = threadIdx.x & 31, w = threadIdx.x >> 5;
    const int wr = w / NCW, wc = w % NCW;
    const int r4 = lane >> 2, kq = lane & 3;
#pragma unroll
    for (int mi = 0; mi < 2; ++mi) {
        int row = wr * 32 + mi * 16 + r4;
#pragma unroll
        for (int ni = 0; ni < NI; ++ni) {
            int col = wc * (NI * 8) + ni * 8 + kq * 2;
            *(float2*)&D[row * SD + col] = make_float2(acc[mi][ni][0], acc[mi][ni][1]);
            *(float2*)&D[(row + 8) * SD + col] = make_float2(acc[mi][ni][2], acc[mi][ni][3]);
        }
    }
}

template <int NI>
__device__ __forceinline__ void frag_store_split(char* Ah, char* Al,
                                                 const float (&a)[2][NI][4],
                                                 int wr, int wc, int qr, int kq) {
#pragma unroll
    for (int mi = 0; mi < 2; ++mi)
#pragma unroll
        for (int h2 = 0; h2 < 2; ++h2) {
            int row = wr * 32 + mi * 16 + h2 * 8 + qr;
#pragma unroll
            for (int ni = 0; ni < NI; ++ni) {
                int col = wc * (NI * 8) + ni * 8 + kq * 2;
                float v0 = a[mi][ni][h2 * 2 + 0], v1 = a[mi][ni][h2 * 2 + 1];
                float h0, l0, h1, l1;
                sp(v0, h0, l0); sp(v1, h1, l1);
                uint32_t off = 2u * (row * SA128 + col);
                *(uint32_t*)(Ah + off) = pk2(h0, h1);
                *(uint32_t*)(Al + off) = pk2(l0, l1);
            }
        }
}

template <int NI>
__device__ __forceinline__ void bias_frag(const float* __restrict__ b,
                                          int wc, int kq, float2 (&o)[NI]) {
#pragma unroll
    for (int ni = 0; ni < NI; ++ni)
        o[ni] = *(const float2*)&b[wc * (NI * 8) + ni * 8 + kq * 2];
}

// ---------------- fills ------------------------------------------------------
__device__ __forceinline__ void split_store4(char* Ah, char* Al, int eoff, float4 v) {
    float h0, l0, h1, l1, h2, l2, h3, l3;
    sp(v.x, h0, l0); sp(v.y, h1, l1); sp(v.z, h2, l2); sp(v.w, h3, l3);
    *(uint2*)(Ah + 2 * eoff) = make_uint2(pk2(h0, h1), pk2(h2, h3));
    *(uint2*)(Al + 2 * eoff) = make_uint2(pk2(l0, l1), pk2(l2, l3));
}

template <int NT>
__device__ __forceinline__ void fill_A128(char* Ah, char* Al,
                                          const float* __restrict__ src,
                                          long r0, int nrows) {
    for (int i = threadIdx.x; i < MT * 32; i += NT) {
        int r = i >> 5, c = (i & 31) * 4;
        float4 v = (r < nrows) ? *(const float4*)&src[(r0 + r) * H + c]
                               : make_float4(0.f, 0.f, 0.f, 0.f);
        split_store4(Ah, Al, r * SA128 + c, v);
    }
}

// ---------------- small kernels ---------------------------------------------
__global__ void zero_m_kernel(size_t n4) {
    float4 z = make_float4(0.f, 0.f, 0.f, 0.f);
    for (size_t i = (size_t)blockIdx.x * blockDim.x + threadIdx.x; i < n4;
         i += (size_t)gridDim.x * blockDim.x)
        ((float4*)g_m)[i] = z;
}

__global__ void prep_kernel(const float* __restrict__ Wkj, const float* __restrict__ Wrbf2,
                            const float* __restrict__ Wdown, const float* __restrict__ Wsbf2,
                            const float* __restrict__ Wup, const float* __restrict__ Wr1a,
                            const float* __restrict__ Wr1b, const float* __restrict__ Wsbf1) {
    int idx = blockIdx.x * 256 + threadIdx.x;
    if (idx < 7 * 16384) {
        int mat = idx >> 14, rem = idx & 16383;
        int n = rem >> 7, k = rem & 127;
        const float* Ws[7] = {Wkj, Wrbf2, Wdown, Wsbf2, Wup, Wr1a, Wr1b};
        float v = Ws[mat][k * H + n];
        float h, l; sp(v, h, l);
        g_WH[idx] = __float2bfloat16(h);
        g_WL[idx] = __float2bfloat16(l);
    } else {
        int rem = idx - 7 * 16384;
        if (rem < 8192) {
            int n = rem >> 6, k = rem & 63;
            float v = (k < 42) ? Wsbf1[k * H + n] : 0.f;
            float h, l; sp(v, h, l);
            g_W1H[rem] = __float2bfloat16(h);
            g_W1L[rem] = __float2bfloat16(l);
        }
    }
}

// ---------------- main kernels ----------------------------------------------
// K1 (256 threads, NI=4): edge_down = silu((silu(x@Wkj+b)*silu(rbf@Wr2+b))@Wdown+b)
__global__ __launch_bounds__(256, 2)
void edge_kernel(const float* __restrict__ x, const float* __restrict__ rbf,
                 const float* __restrict__ b_kj, const float* __restrict__ b_rbf2,
                 const float* __restrict__ b_down, int E) {
    extern __shared__ __align__(16) char sm[];
    uint32_t sb = smem_u32(sm);
    char* Ah = sm + OFF_AH; char* Al = sm + OFF_AL;
    float* D = (float*)(sm + OFF_D);
    const int tid = threadIdx.x, lane = tid & 31, w = tid >> 5;
    const int wr = w >> 2, wc = w & 3, qr = lane >> 2, kq = lane & 3;
    const long e0 = (long)blockIdx.x * MT;
    const int rows = (int)min((long)MT, (long)E - e0);
    float acc[2][4][4], t1[2][4][4];

    copyB_async<128, 256>(sb + OFF_BH, sb + OFF_BL, g_WH + 0 * 16384, g_WL + 0 * 16384);
    fill_A128<256>(Ah, Al, x, e0, rows);
    CP_WAIT0(); __syncthreads();
    warp_gemm<128, SA128, 4>(sb, acc);
    __syncthreads();
    copyB_async<128, 256>(sb + OFF_BH, sb + OFF_BL, g_WH + 1 * 16384, g_WL + 1 * 16384);
    {
        float2 b2[4]; bias_frag<4>(b_kj, wc, kq, b2);
#pragma unroll
        for (int mi = 0; mi < 2; ++mi)
#pragma unroll
            for (int ni = 0; ni < 4; ++ni) {
                t1[mi][ni][0] = fast_silu(acc[mi][ni][0] + b2[ni].x);
                t1[mi][ni][1] = fast_silu(acc[mi][ni][1] + b2[ni].y);
                t1[mi][ni][2] = fast_silu(acc[mi][ni][2] + b2[ni].x);
                t1[mi][ni][3] = fast_silu(acc[mi][ni][3] + b2[ni].y);
            }
    }
    fill_A128<256>(Ah, Al, rbf, e0, rows);
    CP_WAIT0(); __syncthreads();

    warp_gemm<128, SA128, 4>(sb, acc);
    __syncthreads();
    copyB_async<128, 256>(sb + OFF_BH, sb + OFF_BL, g_WH + 2 * 16384, g_WL + 2 * 16384);
    {
        float2 b2[4]; bias_frag<4>(b_rbf2, wc, kq, b2);
#pragma unroll
        for (int mi = 0; mi < 2; ++mi)
#pragma unroll
            for (int ni = 0; ni < 4; ++ni) {
                acc[mi][ni][0] = t1[mi][ni][0] * fast_silu(acc[mi][ni][0] + b2[ni].x);
                acc[mi][ni][1] = t1[mi][ni][1] * fast_silu(acc[mi][ni][1] + b2[ni].y);
                acc[mi][ni][2] = t1[mi][ni][2] * fast_silu(acc[mi][ni][2] + b2[ni].x);
                acc[mi][ni][3] = t1[mi][ni][3] * fast_silu(acc[mi][ni][3] + b2[ni].y);
            }
    }
    frag_store_split<4>(Ah, Al, acc, wr, wc, qr, kq);
    CP_WAIT0(); __syncthreads();

    warp_gemm<128, SA128, 4>(sb, acc);
    __syncthreads();
    acc_to_D<4>(D, acc);
    __syncthreads();
    {
        const int row = tid >> 2, c0 = (tid & 3) * 32;
        if (row < rows) {
            uint32_t* op = g_edge_p + (size_t)(e0 + row) * H + c0;
#pragma unroll
            for (int g = 0; g < 8; ++g) {
                float4 d = *(const float4*)&D[row * SD + c0 + g * 4];
                float4 b = *(const float4*)&b_down[c0 + g * 4];
                float o0 = fast_silu(d.x + b.x), o1 = fast_silu(d.y + b.y);
                float o2 = fast_silu(d.z + b.z), o3 = fast_silu(d.w + b.w);
                float h0, l0, h1, l1, h2, l2, h3, l3;
                sp(o0, h0, l0); sp(o1, h1, l1); sp(o2, h2, l2); sp(o3, h3, l3);
                uint4 pw;
                pw.x = pk2(h0, l0); pw.y = pk2(h1, l1);
                pw.z = pk2(h2, l2); pw.w = pk2(h3, l3);
                *(uint4*)(op + g * 4) = pw;
            }
        }
    }
}

// K2 (128 threads, NI=8): s=silu(silu(sbf@W1)@W2); o=silu((edge[idx_kj]*s)@Wup+b)
// S2 scatters DIRECTLY from fragments via red.v2.
__global__ __launch_bounds__(128, 2)
void trip_kernel(const float* __restrict__ sbf, const int* __restrict__ idx_kj,
                 const int* __restrict__ idx_ji, const float* __restrict__ b_up, int T) {
    extern __shared__ __align__(16) char sm[];
    uint32_t sb = smem_u32(sm);
    char* Ah = sm + OFF_AH; char* Al = sm + OFF_AL;
    int* skj = (int*)(sm + OFF_KJ);
    int* sji = (int*)(sm + OFF_JI);
    const int tid = threadIdx.x, lane = tid & 31, w = tid >> 5;
    const int wr = w >> 1, wc = w & 1, qr = lane >> 2, kq = lane & 3;
    const long t0 = (long)blockIdx.x * MT;
    const int rows = (int)min((long)MT, (long)T - t0);
    float acc[2][8][4];

    if (tid < MT) {
        long t = t0 + tid;
        skj[tid] = (tid < rows) ? idx_kj[t] : 0;
        sji[tid] = (tid < rows) ? idx_ji[t] : 0;
    }

    // S0: sbf @ Wsbf1 (K=64, cols 42..63 zero)
    copyB_async<64, 128>(sb + OFF_BH, sb + OFF_BL, g_W1H, g_W1L);
    for (int i = tid; i < MT * 64; i += 128) {
        int r = i >> 6, c = i & 63;
        float val = (c < 42 && r < rows) ? sbf[(t0 + r) * 42 + c] : 0.f;
        float h, l; sp(val, h, l);
        *(__nv_bfloat16*)(Ah + (r * SA64 + c) * 2) = __float2bfloat16(h);
        *(__nv_bfloat16*)(Al + (r * SA64 + c) * 2) = __float2bfloat16(l);
    }
    CP_WAIT0(); __syncthreads();
    warp_gemm<64, SA64, 8>(sb, acc);
    __syncthreads();
    copyB_async<128, 128>(sb + OFF_BH, sb + OFF_BL, g_WH + 3 * 16384, g_WL + 3 * 16384);
#pragma unroll
    for (int mi = 0; mi < 2; ++mi)
#pragma unroll
        for (int ni = 0; ni < 8; ++ni)
#pragma unroll
            for (int q = 0; q < 4; ++q) acc[mi][ni][q] = fast_silu(acc[mi][ni][q]);
    frag_store_split<8>(Ah, Al, acc, wr, wc, qr, kq);
#pragma unroll
    for (int mi = 0; mi < 2; ++mi)
#pragma unroll
        for (int h2 = 0; h2 < 2; ++h2) {
            int row = wr * 32 + mi * 16 + h2 * 8 + qr;
            size_t e = (size_t)skj[row];
            const uint32_t* pp = g_edge_p + e * H + wc * 64;
            prefetchL2(pp);
            prefetchL2(pp + 32);
        }
    CP_WAIT0(); __syncthreads();

    // S1: @ Wsbf2 ; multiply gathered packed edge_down
    warp_gemm<128, SA128, 8>(sb, acc);
    __syncthreads();
    copyB_async<128, 128>(sb + OFF_BH, sb + OFF_BL, g_WH + 4 * 16384, g_WL + 4 * 16384);
#pragma unroll
    for (int mi = 0; mi < 2; ++mi)
#pragma unroll
        for (int h2 = 0; h2 < 2; ++h2) {
            int row = wr * 32 + mi * 16 + h2 * 8 + qr;
            size_t e = (size_t)skj[row];
            const uint32_t* pp = g_edge_p + e * H + wc * 64 + kq * 2;
#pragma unroll
            for (int ni = 0; ni < 8; ++ni) {
                uint2 pw = *(const uint2*)(pp + ni * 8);
                acc[mi][ni][h2 * 2 + 0] = fast_silu(acc[mi][ni][h2 * 2 + 0]) * unpk(pw.x);
                acc[mi][ni][h2 * 2 + 1] = fast_silu(acc[mi][ni][h2 * 2 + 1]) * unpk(pw.y);
            }
        }
    frag_store_split<8>(Ah, Al, acc, wr, wc, qr, kq);
    CP_WAIT0(); __syncthreads();

    // S2: @ Wup -> silu(.+b_up) -> fragment-direct scatter
    warp_gemm<128, SA128, 8>(sb, acc);
    {
        float2 b2[8]; bias_frag<8>(b_up, wc, kq, b2);
#pragma unroll
        for (int mi = 0; mi < 2; ++mi)
#pragma unroll
            for (int h2 = 0; h2 < 2; ++h2) {
                int row = wr * 32 + mi * 16 + h2 * 8 + qr;
                if (row < rows) {
                    float* mp = g_m + (size_t)sji[row] * H + wc * 64 + kq * 2;
#pragma unroll
                    for (int ni = 0; ni < 8; ++ni) {
                        float o0 = fast_silu(acc[mi][ni][h2 * 2 + 0] + b2[ni].x);
                        float o1 = fast_silu(acc[mi][ni][h2 * 2 + 1] + b2[ni].y);
                        asm volatile("red.global.add.v2.f32 [%0], {%1,%2};"
                                     :: "l"(mp + ni * 8), "f"(o0), "f"(o1)
                                     : "memory");
                    }
                }
            }
    }
}

// K3 (256 threads, NI=4): out = m + silu(silu(m@Wr1a+b)@Wr1b+b) + x
__global__ __launch_bounds__(256, 2)
void res_kernel(const float* __restrict__ x, const float* __restrict__ b_r1a,
                const float* __restrict__ b_r1b, float* __restrict__ out, int E) {
    extern __shared__ __align__(16) char sm[];
    uint32_t sb = smem_u32(sm);
    char* Ah = sm + OFF_AH; char* Al = sm + OFF_AL;
    float* D = (float*)(sm + OFF_D);
    const int tid = threadIdx.x, lane = tid & 31, w = tid >> 5;
    const int wr = w >> 2, wc = w & 3, qr = lane >> 2, kq = lane & 3;
    const long e0 = (long)blockIdx.x * MT;
    const int rows = (int)min((long)MT, (long)E - e0);
    float acc[2][4][4];

    copyB_async<128, 256>(sb + OFF_BH, sb + OFF_BL, g_WH + 5 * 16384, g_WL + 5 * 16384);
    fill_A128<256>(Ah, Al, g_m, e0, rows);
    CP_WAIT0(); __syncthreads();
    warp_gemm<128, SA128, 4>(sb, acc);
    __syncthreads();
    copyB_async<128, 256>(sb + OFF_BH, sb + OFF_BL, g_WH + 6 * 16384, g_WL + 6 * 16384);
    {
        float2 b2[4]; bias_frag<4>(b_r1a, wc, kq, b2);
#pragma unroll
        for (int mi = 0; mi < 2; ++mi)
#pragma unroll
            for (int ni = 0; ni < 4; ++ni) {
                acc[mi][ni][0] = fast_silu(acc[mi][ni][0] + b2[ni].x);
                acc[mi][ni][1] = fast_silu(acc[mi][ni][1] + b2[ni].y);
                acc[mi][ni][2] = fast_silu(acc[mi][ni][2] + b2[ni].x);
                acc[mi][ni][3] = fast_silu(acc[mi][ni][3] + b2[ni].y);
            }
    }
    frag_store_split<4>(Ah, Al, acc, wr, wc, qr, kq);
    CP_WAIT0(); __syncthreads();

    warp_gemm<128, SA128, 4>(sb, acc);
    __syncthreads();
    acc_to_D<4>(D, acc);
    __syncthreads();
    {
        const int row = tid >> 2, c0 = (tid & 3) * 32;
        if (row < rows) {
            const float4* mp = (const float4*)(g_m + (size_t)(e0 + row) * H + c0);
            const float4* xp = (const float4*)(x + (size_t)(e0 + row) * H + c0);
            float4* op = (float4*)(out + (size_t)(e0 + row) * H + c0);
#pragma unroll
            for (int g = 0; g < 8; ++g) {
                float4 d = *(const float4*)&D[row * SD + c0 + g * 4];
                float4 b = *(const float4*)&b_r1b[c0 + g * 4];
                float4 mv = mp[g], xv = xp[g], o;
                o.x = mv.x + fast_silu(d.x + b.x) + xv.x;
                o.y = mv.y + fast_silu(d.y + b.y) + xv.y;
                o.z = mv.z + fast_silu(d.z + b.z) + xv.z;
                o.w = mv.w + fast_silu(d.w + b.w) + xv.w;
                op[g] = o;
            }
        }
    }
}

// ---------------------------------------------------------------------------
extern "C" void kernel_launch(void* const* d_in, const int* in_sizes, int n_in,
                              void* d_out, int out_size) {
    const float* x      = (const float*)d_in[0];
    const float* rbf    = (const float*)d_in[1];
    const float* sbf    = (const float*)d_in[2];
    const int*   idx_kj = (const int*)d_in[3];
    const int*   idx_ji = (const int*)d_in[4];
    const float* W_rbf2 = (const float*)d_in[5];
    const float* b_rbf2 = (const float*)d_in[6];
    const float* W_sbf1 = (const float*)d_in[7];
    const float* W_sbf2 = (const float*)d_in[8];
    const float* W_kj   = (const float*)d_in[9];
    const float* b_kj   = (const float*)d_in[10];
    const float* W_down = (const float*)d_in[11];
    const float* b_down = (const float*)d_in[12];
    const float* W_up   = (const float*)d_in[13];
    const float* b_up   = (const float*)d_in[14];
    const float* W_r1a  = (const float*)d_in[15];
    const float* b_r1a  = (const float*)d_in[16];
    const float* W_r1b  = (const float*)d_in[17];
    const float* b_r1b  = (const float*)d_in[18];
    float* out = (float*)d_out;

    int E = in_sizes[0] / H;
    int T = in_sizes[3];

    cudaFuncSetAttribute(edge_kernel, cudaFuncAttributeMaxDynamicSharedMemorySize, SMEM_BYTES);
    cudaFuncSetAttribute(trip_kernel, cudaFuncAttributeMaxDynamicSharedMemorySize, SMEM_BYTES);
    cudaFuncSetAttribute(res_kernel, cudaFuncAttributeMaxDynamicSharedMemorySize, SMEM_BYTES);

    prep_kernel<<<480, 256>>>(W_kj, W_rbf2, W_down, W_sbf2, W_up, W_r1a, W_r1b, W_sbf1);
    zero_m_kernel<<<2048, 256>>>((size_t)E * H / 4);
    edge_kernel<<<(E + MT - 1) / MT, 256, SMEM_BYTES>>>(x, rbf, b_kj, b_rbf2, b_down, E);
    trip_kernel<<<(T + MT - 1) / MT, 128, SMEM_BYTES>>>(sbf, idx_kj, idx_ji, b_up, T);
    res_kernel<<<(E + MT - 1) / MT, 256, SMEM_BYTES>>>(x, b_r1a, b_r1b, out, E);
}